// round 10
// baseline (speedup 1.0000x reference)
#include <cuda_runtime.h>
#include <cuda_bf16.h>
#include <stdint.h>

// ---------------------------------------------------------------------------
// Problem constants
// ---------------------------------------------------------------------------
#define NPTS  128
#define W     1024
#define L     1024
#define MTOT  2048          // 2 channels * W
#define SIGMA 32.0f

// Logical GEMM K' = 384 = [Ah|Al|Ah] x [Bh|Bh|Bl]  (dropped Al*Bl ~ 2^-18)
// Physical storage: A = [Ah|Al] (16 k-steps), B = [Bh|Bl] (16 k-steps)
#define NKS_LOG  24
#define NKS_PHYS 16
#define BM 128
#define BN 128

// ---------------------------------------------------------------------------
// Device scratch (no allocation):
//   gT   : radial Gaussian table, gT[d] = exp(-d^2/(2 sigma^2)), d in [0,1024)
//   gAp  : [ksp(16)][mt(128)][lane(32)][reg(4)][half(2)] bf16  (1 MB)
//   gBp  : [ksp(16)][nt(128)][lane(32)][reg(2)][half(2)] bf16  (512 KB)
// ksp 0-7 = hi part, ksp 8-15 = lo part
// ---------------------------------------------------------------------------
__device__ float gT[1024];
__device__ __align__(16) __nv_bfloat16 gAp[NKS_PHYS * (MTOT / 16) * 32 * 8];
__device__ __align__(16) __nv_bfloat16 gBp[NKS_PHYS * (L / 8) * 32 * 4];

// ---------------------------------------------------------------------------
// Kernel 0: radial exp table (1024 exps total).
// ---------------------------------------------------------------------------
__global__ void table_kernel()
{
    const int d = blockIdx.x * 256 + threadIdx.x;
    const float fd = (float)d;
    gT[d] = __expf(-fd * fd * (1.0f / (2.0f * SIGMA * SIGMA)));
}

// ---------------------------------------------------------------------------
// Kernel 1: fragment tables via table lookup; one thread writes BOTH the hi
// and lo fragment words (coalesced uint4/uint2 stores).
// grid 192 x 256: blocks [0,128) -> A, [128,192) -> B... (A:32768, B:32768 thr)
// Actually: blocks [0,128) A (32768 threads), [128,256) B (32768 threads).
//
// mma.sync m16n8k16 .row.col fragment layout (PTX ISA):
//   A slot(reg,half): rm = (lane>>2)+8*(reg&1); rk = (reg>>1)*8+(lane&3)*2+half
//   B slot(reg,half): y_in = lane>>2;           rk = reg*8+(lane&3)*2+half
// coords are int32 (JAX x64 disabled downcasts jnp.int64 -> int32)
// ---------------------------------------------------------------------------
__global__ void frag_kernel(const float* __restrict__ vecs,
                            const int* __restrict__ xc,
                            const int* __restrict__ yc)
{
    const int bid = blockIdx.x;

    if (bid < 128) {
        // ---- A fragments: gid in [0, 32768), ksp_hi = gid>>12 in [0,8) ----
        const int gid  = bid * 256 + threadIdx.x;
        const int lane = gid & 31;
        const int mt   = (gid >> 5) & 127;
        const int ksp  = gid >> 12;                 // hi stage 0..7

        const int c = (mt * 16) >> 10;              // channel (fixed per mt)
        const float* vc = vecs + c * NPTS;

        union { uint4 u; __nv_bfloat16 v[8]; } hi, lo;
#pragma unroll
        for (int reg = 0; reg < 4; reg++) {
#pragma unroll
            for (int half = 0; half < 2; half++) {
                const int rm = (lane >> 2) + 8 * (reg & 1);
                const int rk = ((reg >> 1) << 3) + ((lane & 3) << 1) + half;
                const int m  = mt * 16 + rm;
                const int n  = ksp * 16 + rk;       // point index 0..127
                const int x  = m & 1023;
                const int d  = abs(x - xc[n]);
                const float a = gT[d] * vc[n];
                const __nv_bfloat16 ah = __float2bfloat16(a);
                hi.v[reg * 2 + half] = ah;
                lo.v[reg * 2 + half] =
                    __float2bfloat16(a - __bfloat162float(ah));
            }
        }
        ((uint4*)gAp)[gid]         = hi.u;          // stage ksp
        ((uint4*)gAp)[gid + 32768] = lo.u;          // stage ksp+8
    } else {
        // ---- B fragments: gid in [0, 32768), ksp_hi = gid>>12 in [0,8) ----
        const int gid  = (bid - 128) * 256 + threadIdx.x;
        const int lane = gid & 31;
        const int nt   = (gid >> 5) & 127;
        const int ksp  = gid >> 12;

        const int y = nt * 8 + (lane >> 2);
        union { uint2 u; __nv_bfloat16 v[4]; } hi, lo;
#pragma unroll
        for (int reg = 0; reg < 2; reg++) {
#pragma unroll
            for (int half = 0; half < 2; half++) {
                const int rk = (reg << 3) + ((lane & 3) << 1) + half;
                const int n  = ksp * 16 + rk;
                const int d  = abs(y - yc[n]);
                const float e = gT[d];
                const __nv_bfloat16 bh = __float2bfloat16(e);
                hi.v[reg * 2 + half] = bh;
                lo.v[reg * 2 + half] =
                    __float2bfloat16(e - __bfloat162float(bh));
            }
        }
        ((uint2*)gBp)[gid]         = hi.u;
        ((uint2*)gBp)[gid + 32768] = lo.u;
    }
}

// ---------------------------------------------------------------------------
// Kernel 2: HMMA GEMM, whole-K smem resident (128 KB), 3 barriers total.
// CTA tile 128x128, 512 threads = 16 warps in 4(m) x 4(n); warp tile 32x32.
// ---------------------------------------------------------------------------
__device__ __forceinline__ void mma16816(float* c, const uint32_t* a,
                                         const uint32_t* b) {
    asm volatile(
        "mma.sync.aligned.m16n8k16.row.col.f32.bf16.bf16.f32 "
        "{%0,%1,%2,%3}, {%4,%5,%6,%7}, {%8,%9}, {%0,%1,%2,%3};"
        : "+f"(c[0]), "+f"(c[1]), "+f"(c[2]), "+f"(c[3])
        : "r"(a[0]), "r"(a[1]), "r"(a[2]), "r"(a[3]),
          "r"(b[0]), "r"(b[1]));
}
__device__ __forceinline__ uint32_t smem_u32(const void* p) {
    uint32_t a;
    asm("{ .reg .u64 t; cvta.to.shared.u64 t, %1; cvt.u32.u64 %0, t; }"
        : "=r"(a) : "l"(p));
    return a;
}
__device__ __forceinline__ void cp16(uint32_t dst, const void* src) {
    asm volatile("cp.async.cg.shared.global [%0], [%1], 16;"
                 :: "r"(dst), "l"(src));
}
#define CP_COMMIT() asm volatile("cp.async.commit_group;" ::: "memory")

#define SMEM_BYTES (NKS_PHYS * 4096 * 2)   // 128 KB: A stages then B stages

extern __shared__ char smem_dyn[];

__global__ void __launch_bounds__(512, 1)
gemm_mma_kernel(float* __restrict__ out)
{
    char* sA = smem_dyn;                       // 16 stages x 4 KB
    char* sB = smem_dyn + NKS_PHYS * 4096;     // 16 stages x 4 KB

    const int tid  = threadIdx.x;
    const int wid  = tid >> 5;
    const int lane = tid & 31;

    const int y_base = blockIdx.x * BN;        // 8 blocks
    const int m_base = blockIdx.y * BM;        // 16 blocks

    const int wm = wid >> 2;                   // 0..3 (m dir, 32 rows)
    const int wn = wid & 3;                    // 0..3 (n dir, 32 cols)

    const uint32_t sa_base = smem_u32(sA);
    const uint32_t sb_base = smem_u32(sB);

    // Per-CTA contiguous 4 KB global slices per physical k-step
    const char* gA = (const char*)gAp + (size_t)(m_base / 16) * 512;
    const char* gB = (const char*)gBp + (size_t)(y_base / 8) * 256;
    const size_t A_KS = (size_t)(MTOT / 16) * 512;   // 65536 B
    const size_t B_KS = (size_t)(L / 8) * 256;       // 32768 B

    // Issue ALL 16 stage fills up front (one commit group per phys k-step).
    // Threads 0-255 fill A (4 KB), threads 256-511 fill B (4 KB).
    const bool isA = (tid < 256);
    const int  ft  = isA ? tid : (tid - 256);
#pragma unroll
    for (int s = 0; s < NKS_PHYS; s++) {
        if (isA)
            cp16(sa_base + s * 4096 + ft * 16, gA + (size_t)s * A_KS + ft * 16);
        else
            cp16(sb_base + s * 4096 + ft * 16, gB + (size_t)s * B_KS + ft * 16);
        CP_COMMIT();
    }

    float acc[2][4][4] = {};                   // [im][in][creg]

    const uint32_t a_off = wm * 1024 + lane * 16;   // 2 mt x 512 B
    const uint32_t b_off = wn * 1024 + lane * 8;    // 4 nt x 256 B

    // 24 logical k-steps in chunks; barriers only at chunk heads.
#pragma unroll
    for (int Lk = 0; Lk < NKS_LOG; Lk++) {
        if (Lk == 0) {
            asm volatile("cp.async.wait_group 10;" ::: "memory"); // 0-5 done
            __syncthreads();
        } else if (Lk == 6) {
            asm volatile("cp.async.wait_group 4;" ::: "memory");  // 0-11 done
            __syncthreads();
        } else if (Lk == 12) {
            asm volatile("cp.async.wait_group 0;" ::: "memory");  // all done
            __syncthreads();
        }

        const int ap = (Lk < 16) ? Lk : Lk - 16;   // [Ah|Al|Ah]
        const int bp = (Lk < 8)  ? Lk : Lk - 8;    // [Bh|Bh|Bl]

        uint4 a[2];
        uint2 b[4];
#pragma unroll
        for (int im = 0; im < 2; im++)
            a[im] = *(const uint4*)(sA + ap * 4096 + a_off + im * 512);
#pragma unroll
        for (int in = 0; in < 4; in++)
            b[in] = *(const uint2*)(sB + bp * 4096 + b_off + in * 256);

#pragma unroll
        for (int im = 0; im < 2; im++)
#pragma unroll
            for (int in = 0; in < 4; in++)
                mma16816(acc[im][in], (const uint32_t*)&a[im],
                         (const uint32_t*)&b[in]);
    }

    // Epilogue: c0,c1 = (row g, cols 2t,2t+1); c2,c3 = (row g+8)
    const int g = lane >> 2;
    const int t = lane & 3;
#pragma unroll
    for (int im = 0; im < 2; im++) {
        const int row0 = m_base + wm * 32 + im * 16 + g;
#pragma unroll
        for (int in = 0; in < 4; in++) {
            const int col = y_base + wn * 32 + in * 8 + t * 2;
            float2* p0 = (float2*)(out + (size_t)row0 * L + col);
            float2* p1 = (float2*)(out + (size_t)(row0 + 8) * L + col);
            *p0 = make_float2(acc[im][in][0], acc[im][in][1]);
            *p1 = make_float2(acc[im][in][2], acc[im][in][3]);
        }
    }
}

// ---------------------------------------------------------------------------
extern "C" void kernel_launch(void* const* d_in, const int* in_sizes, int n_in,
                              void* d_out, int out_size)
{
    const float* vecs = (const float*)d_in[0];   // [2,128] fp32
    const int*   xc   = (const int*)d_in[1];     // [128] int32
    const int*   yc   = (const int*)d_in[2];     // [128] int32
    float* out = (float*)d_out;                  // [1,2,1024,1024] fp32

    (void)in_sizes; (void)n_in; (void)out_size;

    table_kernel<<<4, 256>>>();
    frag_kernel<<<256, 256>>>(vecs, xc, yc);

    cudaFuncSetAttribute(gemm_mma_kernel,
                         cudaFuncAttributeMaxDynamicSharedMemorySize,
                         SMEM_BYTES);
    dim3 grid(L / BN, MTOT / BM);   // (8, 16) = 128 CTAs, one wave
    gemm_mma_kernel<<<grid, 512, SMEM_BYTES>>>(out);
}

// round 13
// speedup vs baseline: 1.1400x; 1.1400x over previous
#include <cuda_runtime.h>
#include <cuda_bf16.h>
#include <stdint.h>

// ---------------------------------------------------------------------------
// Problem constants
// ---------------------------------------------------------------------------
#define NPTS  128
#define W     1024
#define L     1024
#define MTOT  2048          // 2 channels * W
#define SIGMA 32.0f

// Logical GEMM K' = 384 = [Ah|Al|Ah] x [Bh|Bh|Bl]  (dropped Al*Bl ~ 2^-18)
// Physical storage: A = [Ah|Al] (16 k-steps), B = [Bh|Bl] (16 k-steps)
#define NKS_LOG  24
#define NKS_PHYS 16
#define BM 128
#define BN 128

// ---------------------------------------------------------------------------
// Device scratch (no allocation):
//   gAp  : [ksp(16)][mt(128)][lane(32)][reg(4)][half(2)] bf16  (1 MB)
//   gBp  : [ksp(16)][nt(128)][lane(32)][reg(2)][half(2)] bf16  (512 KB)
// ksp 0-7 = hi part, ksp 8-15 = lo part
// ---------------------------------------------------------------------------
__device__ __align__(16) __nv_bfloat16 gAp[NKS_PHYS * (MTOT / 16) * 32 * 8];
__device__ __align__(16) __nv_bfloat16 gBp[NKS_PHYS * (L / 8) * 32 * 4];

// ---------------------------------------------------------------------------
// Kernel 1: fragment tables. Each block first builds a 1024-entry radial
// Gaussian table in SHARED memory (4 exps/thread), then does table lookups.
// One thread writes BOTH the hi and lo fragment words (coalesced stores).
// grid 256 x 256: blocks [0,128) -> A (uint4/thread), [128,256) -> B (uint2).
//
// mma.sync m16n8k16 .row.col fragment layout (PTX ISA):
//   A slot(reg,half): rm = (lane>>2)+8*(reg&1); rk = (reg>>1)*8+(lane&3)*2+half
//   B slot(reg,half): y_in = lane>>2;           rk = reg*8+(lane&3)*2+half
// coords are int32 (JAX x64 disabled downcasts jnp.int64 -> int32)
// ---------------------------------------------------------------------------
__global__ void __launch_bounds__(256)
frag_kernel(const float* __restrict__ vecs,
            const int* __restrict__ xc,
            const int* __restrict__ yc)
{
    __shared__ float sT[1024];

    // block-local radial table: exp(-d^2 / (2 sigma^2))
    {
        const float inv2s2 = 1.0f / (2.0f * SIGMA * SIGMA);
#pragma unroll
        for (int j = 0; j < 4; j++) {
            const int d = j * 256 + threadIdx.x;
            const float fd = (float)d;
            sT[d] = __expf(-fd * fd * inv2s2);
        }
    }
    __syncthreads();

    const int bid = blockIdx.x;

    if (bid < 128) {
        // ---- A fragments: gid in [0, 32768), ksp = gid>>12 in [0,8) ----
        const int gid  = bid * 256 + threadIdx.x;
        const int lane = gid & 31;
        const int mt   = (gid >> 5) & 127;
        const int ksp  = gid >> 12;                 // hi stage 0..7

        const int c = (mt * 16) >> 10;              // channel (fixed per mt)
        const float* vc = vecs + c * NPTS;

        union { uint4 u; __nv_bfloat16 v[8]; } hi, lo;
#pragma unroll
        for (int reg = 0; reg < 4; reg++) {
#pragma unroll
            for (int half = 0; half < 2; half++) {
                const int rm = (lane >> 2) + 8 * (reg & 1);
                const int rk = ((reg >> 1) << 3) + ((lane & 3) << 1) + half;
                const int m  = mt * 16 + rm;
                const int n  = ksp * 16 + rk;       // point index 0..127
                const int x  = m & 1023;
                const int d  = abs(x - xc[n]);
                const float a = sT[d] * vc[n];
                const __nv_bfloat16 ah = __float2bfloat16(a);
                hi.v[reg * 2 + half] = ah;
                lo.v[reg * 2 + half] =
                    __float2bfloat16(a - __bfloat162float(ah));
            }
        }
        ((uint4*)gAp)[gid]         = hi.u;          // stage ksp
        ((uint4*)gAp)[gid + 32768] = lo.u;          // stage ksp+8
    } else {
        // ---- B fragments: gid in [0, 32768), ksp = gid>>12 in [0,8) ----
        const int gid  = (bid - 128) * 256 + threadIdx.x;
        const int lane = gid & 31;
        const int nt   = (gid >> 5) & 127;
        const int ksp  = gid >> 12;

        const int y = nt * 8 + (lane >> 2);
        union { uint2 u; __nv_bfloat16 v[4]; } hi, lo;
#pragma unroll
        for (int reg = 0; reg < 2; reg++) {
#pragma unroll
            for (int half = 0; half < 2; half++) {
                const int rk = (reg << 3) + ((lane & 3) << 1) + half;
                const int n  = ksp * 16 + rk;
                const int d  = abs(y - yc[n]);
                const float e = sT[d];
                const __nv_bfloat16 bh = __float2bfloat16(e);
                hi.v[reg * 2 + half] = bh;
                lo.v[reg * 2 + half] =
                    __float2bfloat16(e - __bfloat162float(bh));
            }
        }
        ((uint2*)gBp)[gid]         = hi.u;
        ((uint2*)gBp)[gid + 32768] = lo.u;
    }
}

// ---------------------------------------------------------------------------
// Kernel 2: HMMA GEMM, whole-K smem resident (128 KB), 3 barriers total.
// CTA tile 128x128, 512 threads = 16 warps in 4(m) x 4(n); warp tile 32x32.
// ---------------------------------------------------------------------------
__device__ __forceinline__ void mma16816(float* c, const uint32_t* a,
                                         const uint32_t* b) {
    asm volatile(
        "mma.sync.aligned.m16n8k16.row.col.f32.bf16.bf16.f32 "
        "{%0,%1,%2,%3}, {%4,%5,%6,%7}, {%8,%9}, {%0,%1,%2,%3};"
        : "+f"(c[0]), "+f"(c[1]), "+f"(c[2]), "+f"(c[3])
        : "r"(a[0]), "r"(a[1]), "r"(a[2]), "r"(a[3]),
          "r"(b[0]), "r"(b[1]));
}
__device__ __forceinline__ uint32_t smem_u32(const void* p) {
    uint32_t a;
    asm("{ .reg .u64 t; cvta.to.shared.u64 t, %1; cvt.u32.u64 %0, t; }"
        : "=r"(a) : "l"(p));
    return a;
}
__device__ __forceinline__ void cp16(uint32_t dst, const void* src) {
    asm volatile("cp.async.cg.shared.global [%0], [%1], 16;"
                 :: "r"(dst), "l"(src));
}
#define CP_COMMIT() asm volatile("cp.async.commit_group;" ::: "memory")

#define SMEM_BYTES (NKS_PHYS * 4096 * 2)   // 128 KB: A stages then B stages

extern __shared__ char smem_dyn[];

__global__ void __launch_bounds__(512, 1)
gemm_mma_kernel(float* __restrict__ out)
{
    char* sA = smem_dyn;                       // 16 stages x 4 KB
    char* sB = smem_dyn + NKS_PHYS * 4096;     // 16 stages x 4 KB

    const int tid  = threadIdx.x;
    const int wid  = tid >> 5;
    const int lane = tid & 31;

    const int y_base = blockIdx.x * BN;        // 8 blocks
    const int m_base = blockIdx.y * BM;        // 16 blocks

    const int wm = wid >> 2;                   // 0..3 (m dir, 32 rows)
    const int wn = wid & 3;                    // 0..3 (n dir, 32 cols)

    const uint32_t sa_base = smem_u32(sA);
    const uint32_t sb_base = smem_u32(sB);

    // Per-CTA contiguous 4 KB global slices per physical k-step
    const char* gA = (const char*)gAp + (size_t)(m_base / 16) * 512;
    const char* gB = (const char*)gBp + (size_t)(y_base / 8) * 256;
    const size_t A_KS = (size_t)(MTOT / 16) * 512;   // 65536 B
    const size_t B_KS = (size_t)(L / 8) * 256;       // 32768 B

    // Issue ALL 16 stage fills up front (one commit group per phys k-step).
    // Threads 0-255 fill A (4 KB), threads 256-511 fill B (4 KB).
    const bool isA = (tid < 256);
    const int  ft  = isA ? tid : (tid - 256);
#pragma unroll
    for (int s = 0; s < NKS_PHYS; s++) {
        if (isA)
            cp16(sa_base + s * 4096 + ft * 16, gA + (size_t)s * A_KS + ft * 16);
        else
            cp16(sb_base + s * 4096 + ft * 16, gB + (size_t)s * B_KS + ft * 16);
        CP_COMMIT();
    }

    float acc[2][4][4] = {};                   // [im][in][creg]

    const uint32_t a_off = wm * 1024 + lane * 16;   // 2 mt x 512 B
    const uint32_t b_off = wn * 1024 + lane * 8;    // 4 nt x 256 B

    // 24 logical k-steps in chunks; barriers only at chunk heads.
#pragma unroll
    for (int Lk = 0; Lk < NKS_LOG; Lk++) {
        if (Lk == 0) {
            asm volatile("cp.async.wait_group 10;" ::: "memory"); // 0-5 done
            __syncthreads();
        } else if (Lk == 6) {
            asm volatile("cp.async.wait_group 4;" ::: "memory");  // 0-11 done
            __syncthreads();
        } else if (Lk == 12) {
            asm volatile("cp.async.wait_group 0;" ::: "memory");  // all done
            __syncthreads();
        }

        const int ap = (Lk < 16) ? Lk : Lk - 16;   // [Ah|Al|Ah]
        const int bp = (Lk < 8)  ? Lk : Lk - 8;    // [Bh|Bh|Bl]

        uint4 a[2];
        uint2 b[4];
#pragma unroll
        for (int im = 0; im < 2; im++)
            a[im] = *(const uint4*)(sA + ap * 4096 + a_off + im * 512);
#pragma unroll
        for (int in = 0; in < 4; in++)
            b[in] = *(const uint2*)(sB + bp * 4096 + b_off + in * 256);

#pragma unroll
        for (int im = 0; im < 2; im++)
#pragma unroll
            for (int in = 0; in < 4; in++)
                mma16816(acc[im][in], (const uint32_t*)&a[im],
                         (const uint32_t*)&b[in]);
    }

    // Epilogue: c0,c1 = (row g, cols 2t,2t+1); c2,c3 = (row g+8)
    const int g = lane >> 2;
    const int t = lane & 3;
#pragma unroll
    for (int im = 0; im < 2; im++) {
        const int row0 = m_base + wm * 32 + im * 16 + g;
#pragma unroll
        for (int in = 0; in < 4; in++) {
            const int col = y_base + wn * 32 + in * 8 + t * 2;
            float2* p0 = (float2*)(out + (size_t)row0 * L + col);
            float2* p1 = (float2*)(out + (size_t)(row0 + 8) * L + col);
            *p0 = make_float2(acc[im][in][0], acc[im][in][1]);
            *p1 = make_float2(acc[im][in][2], acc[im][in][3]);
        }
    }
}

// ---------------------------------------------------------------------------
extern "C" void kernel_launch(void* const* d_in, const int* in_sizes, int n_in,
                              void* d_out, int out_size)
{
    const float* vecs = (const float*)d_in[0];   // [2,128] fp32
    const int*   xc   = (const int*)d_in[1];     // [128] int32
    const int*   yc   = (const int*)d_in[2];     // [128] int32
    float* out = (float*)d_out;                  // [1,2,1024,1024] fp32

    (void)in_sizes; (void)n_in; (void)out_size;

    frag_kernel<<<256, 256>>>(vecs, xc, yc);

    cudaFuncSetAttribute(gemm_mma_kernel,
                         cudaFuncAttributeMaxDynamicSharedMemorySize,
                         SMEM_BYTES);
    dim3 grid(L / BN, MTOT / BM);   // (8, 16) = 128 CTAs, one wave
    gemm_mma_kernel<<<grid, 512, SMEM_BYTES>>>(out);
}

// round 17
// speedup vs baseline: 1.3571x; 1.1905x over previous
#include <cuda_runtime.h>
#include <cuda_fp16.h>
#include <stdint.h>

// ---------------------------------------------------------------------------
// Problem constants
// ---------------------------------------------------------------------------
#define NPTS  128
#define W     1024
#define L     1024
#define MTOT  2048          // 2 channels * W
#define SIGMA 32.0f

// Single-pass fp16 GEMM: K = 128 (fp16 products are exact in fp32 accum;
// error = input rounding only, ~4e-4 RMS on the field norm)
#define NKS 8               // 8 k-steps of 16
#define BM 128
#define BN 128

// ---------------------------------------------------------------------------
// Device scratch (no allocation):
//   gAp : [ks(8)][mt(128)][lane(32)][reg(4)][half(2)] fp16  (512 KB)
//   gBp : [ks(8)][nt(128)][lane(32)][reg(2)][half(2)] fp16  (256 KB)
// ---------------------------------------------------------------------------
__device__ __align__(16) __half gAp[NKS * (MTOT / 16) * 32 * 8];
__device__ __align__(16) __half gBp[NKS * (L / 8) * 32 * 4];

// ---------------------------------------------------------------------------
// Kernel 1: fragment tables. Each block builds a 1024-entry radial Gaussian
// table in shared memory (4 exps/thread), then does lookups + fp16 rounding,
// one coalesced fragment-word store per thread.
// grid 256 x 256: blocks [0,128) -> A (uint4/thread), [128,256) -> B (uint2).
//
// mma.sync m16n8k16 .row.col fragment layout (PTX ISA):
//   A slot(reg,half): rm = (lane>>2)+8*(reg&1); rk = (reg>>1)*8+(lane&3)*2+half
//   B slot(reg,half): y_in = lane>>2;           rk = reg*8+(lane&3)*2+half
// coords are int32 (JAX x64 disabled downcasts jnp.int64 -> int32)
// ---------------------------------------------------------------------------
__global__ void __launch_bounds__(256)
frag_kernel(const float* __restrict__ vecs,
            const int* __restrict__ xc,
            const int* __restrict__ yc)
{
    __shared__ float sT[1024];
    {
        const float inv2s2 = 1.0f / (2.0f * SIGMA * SIGMA);
#pragma unroll
        for (int j = 0; j < 4; j++) {
            const int d = j * 256 + threadIdx.x;
            const float fd = (float)d;
            sT[d] = __expf(-fd * fd * inv2s2);
        }
    }
    __syncthreads();

    const int bid = blockIdx.x;

    if (bid < 128) {
        // ---- A fragments: gid in [0, 32768), ks = gid>>12 in [0,8) ----
        const int gid  = bid * 256 + threadIdx.x;
        const int lane = gid & 31;
        const int mt   = (gid >> 5) & 127;
        const int ks   = gid >> 12;

        const int c = (mt * 16) >> 10;              // channel (fixed per mt)
        const float* vc = vecs + c * NPTS;

        union { uint4 u; __half v[8]; } pack;
#pragma unroll
        for (int reg = 0; reg < 4; reg++) {
#pragma unroll
            for (int half = 0; half < 2; half++) {
                const int rm = (lane >> 2) + 8 * (reg & 1);
                const int rk = ((reg >> 1) << 3) + ((lane & 3) << 1) + half;
                const int m  = mt * 16 + rm;
                const int n  = ks * 16 + rk;        // point index 0..127
                const int x  = m & 1023;
                const int d  = abs(x - xc[n]);
                pack.v[reg * 2 + half] = __float2half(sT[d] * vc[n]);
            }
        }
        ((uint4*)gAp)[gid] = pack.u;
    } else {
        // ---- B fragments: gid in [0, 32768), ks = gid>>12 in [0,8) ----
        const int gid  = (bid - 128) * 256 + threadIdx.x;
        const int lane = gid & 31;
        const int nt   = (gid >> 5) & 127;
        const int ks   = gid >> 12;

        const int y = nt * 8 + (lane >> 2);
        union { uint2 u; __half v[4]; } pack;
#pragma unroll
        for (int reg = 0; reg < 2; reg++) {
#pragma unroll
            for (int half = 0; half < 2; half++) {
                const int rk = (reg << 3) + ((lane & 3) << 1) + half;
                const int n  = ks * 16 + rk;
                const int d  = abs(y - yc[n]);
                pack.v[reg * 2 + half] = __float2half(sT[d]);
            }
        }
        ((uint2*)gBp)[gid] = pack.u;
    }
}

// ---------------------------------------------------------------------------
// Kernel 2: fp16 HMMA GEMM, whole-K smem resident (64 KB), 2 barriers total.
// CTA tile 128x128, 512 threads = 16 warps in 4(m) x 4(n); warp tile 32x32.
// ---------------------------------------------------------------------------
__device__ __forceinline__ void mma16816(float* c, const uint32_t* a,
                                         const uint32_t* b) {
    asm volatile(
        "mma.sync.aligned.m16n8k16.row.col.f32.f16.f16.f32 "
        "{%0,%1,%2,%3}, {%4,%5,%6,%7}, {%8,%9}, {%0,%1,%2,%3};"
        : "+f"(c[0]), "+f"(c[1]), "+f"(c[2]), "+f"(c[3])
        : "r"(a[0]), "r"(a[1]), "r"(a[2]), "r"(a[3]),
          "r"(b[0]), "r"(b[1]));
}
__device__ __forceinline__ uint32_t smem_u32(const void* p) {
    uint32_t a;
    asm("{ .reg .u64 t; cvta.to.shared.u64 t, %1; cvt.u32.u64 %0, t; }"
        : "=r"(a) : "l"(p));
    return a;
}
__device__ __forceinline__ void cp16(uint32_t dst, const void* src) {
    asm volatile("cp.async.cg.shared.global [%0], [%1], 16;"
                 :: "r"(dst), "l"(src));
}
#define CP_COMMIT() asm volatile("cp.async.commit_group;" ::: "memory")

#define SMEM_BYTES (NKS * 4096 * 2)   // 64 KB: A stages then B stages

extern __shared__ char smem_dyn[];

__global__ void __launch_bounds__(512, 1)
gemm_mma_kernel(float* __restrict__ out)
{
    char* sA = smem_dyn;                 // 8 stages x 4 KB
    char* sB = smem_dyn + NKS * 4096;    // 8 stages x 4 KB

    const int tid  = threadIdx.x;
    const int wid  = tid >> 5;
    const int lane = tid & 31;

    const int y_base = blockIdx.x * BN;  // 8 blocks
    const int m_base = blockIdx.y * BM;  // 16 blocks

    const int wm = wid >> 2;             // 0..3 (m dir, 32 rows)
    const int wn = wid & 3;              // 0..3 (n dir, 32 cols)

    const uint32_t sa_base = smem_u32(sA);
    const uint32_t sb_base = smem_u32(sB);

    // Per-CTA contiguous 4 KB global slices per k-step
    const char* gA = (const char*)gAp + (size_t)(m_base / 16) * 512;
    const char* gB = (const char*)gBp + (size_t)(y_base / 8) * 256;
    const size_t A_KS = (size_t)(MTOT / 16) * 512;   // 65536 B
    const size_t B_KS = (size_t)(L / 8) * 256;       // 32768 B

    // Issue ALL 8 stage fills up front (one commit group per k-step).
    // Threads 0-255 fill A (4 KB), threads 256-511 fill B (4 KB).
    const bool isA = (tid < 256);
    const int  ft  = isA ? tid : (tid - 256);
#pragma unroll
    for (int s = 0; s < NKS; s++) {
        if (isA)
            cp16(sa_base + s * 4096 + ft * 16, gA + (size_t)s * A_KS + ft * 16);
        else
            cp16(sb_base + s * 4096 + ft * 16, gB + (size_t)s * B_KS + ft * 16);
        CP_COMMIT();
    }

    float acc[2][4][4] = {};             // [im][in][creg]

    const uint32_t a_off = wm * 1024 + lane * 16;   // 2 mt x 512 B
    const uint32_t b_off = wn * 1024 + lane * 8;    // 4 nt x 256 B

    // 8 k-steps; barriers only at chunk heads (2 total).
#pragma unroll
    for (int Lk = 0; Lk < NKS; Lk++) {
        if (Lk == 0) {
            asm volatile("cp.async.wait_group 4;" ::: "memory"); // 0-3 done
            __syncthreads();
        } else if (Lk == 4) {
            asm volatile("cp.async.wait_group 0;" ::: "memory"); // all done
            __syncthreads();
        }

        uint4 a[2];
        uint2 b[4];
#pragma unroll
        for (int im = 0; im < 2; im++)
            a[im] = *(const uint4*)(sA + Lk * 4096 + a_off + im * 512);
#pragma unroll
        for (int in = 0; in < 4; in++)
            b[in] = *(const uint2*)(sB + Lk * 4096 + b_off + in * 256);

#pragma unroll
        for (int im = 0; im < 2; im++)
#pragma unroll
            for (int in = 0; in < 4; in++)
                mma16816(acc[im][in], (const uint32_t*)&a[im],
                         (const uint32_t*)&b[in]);
    }

    // Epilogue: c0,c1 = (row g, cols 2t,2t+1); c2,c3 = (row g+8)
    const int g = lane >> 2;
    const int t = lane & 3;
#pragma unroll
    for (int im = 0; im < 2; im++) {
        const int row0 = m_base + wm * 32 + im * 16 + g;
#pragma unroll
        for (int in = 0; in < 4; in++) {
            const int col = y_base + wn * 32 + in * 8 + t * 2;
            float2* p0 = (float2*)(out + (size_t)row0 * L + col);
            float2* p1 = (float2*)(out + (size_t)(row0 + 8) * L + col);
            *p0 = make_float2(acc[im][in][0], acc[im][in][1]);
            *p1 = make_float2(acc[im][in][2], acc[im][in][3]);
        }
    }
}

// ---------------------------------------------------------------------------
extern "C" void kernel_launch(void* const* d_in, const int* in_sizes, int n_in,
                              void* d_out, int out_size)
{
    const float* vecs = (const float*)d_in[0];   // [2,128] fp32
    const int*   xc   = (const int*)d_in[1];     // [128] int32
    const int*   yc   = (const int*)d_in[2];     // [128] int32
    float* out = (float*)d_out;                  // [1,2,1024,1024] fp32

    (void)in_sizes; (void)n_in; (void)out_size;

    frag_kernel<<<256, 256>>>(vecs, xc, yc);

    cudaFuncSetAttribute(gemm_mma_kernel,
                         cudaFuncAttributeMaxDynamicSharedMemorySize,
                         SMEM_BYTES);
    dim3 grid(L / BN, MTOT / BM);   // (8, 16) = 128 CTAs, one wave
    gemm_mma_kernel<<<grid, 512, SMEM_BYTES>>>(out);
}